// round 10
// baseline (speedup 1.0000x reference)
#include <cuda_runtime.h>
#include <cuda_bf16.h>
#include <math.h>

#define HDIM 512
#define NDIM 32
#define LLEN 4096
#define LF   2049   // LLEN/2 + 1

__device__ float2 g_kf[HDIM * LF];
__device__ float2 g_tw[1024];      // W^j = e^{+2*pi*i*j/4096}, j < 1024

// ---------------- packed f32x2 + fast-rcp helpers ---------------------------
typedef unsigned long long u64;
__device__ __forceinline__ u64 pk(float lo, float hi) {
    u64 r; asm("mov.b64 %0,{%1,%2};" : "=l"(r) : "f"(lo), "f"(hi)); return r;
}
__device__ __forceinline__ void upk(float& lo, float& hi, u64 v) {
    asm("mov.b64 {%0,%1},%2;" : "=f"(lo), "=f"(hi) : "l"(v));
}
__device__ __forceinline__ u64 f2add(u64 a, u64 b) {
    u64 d; asm("add.rn.f32x2 %0,%1,%2;" : "=l"(d) : "l"(a), "l"(b)); return d;
}
__device__ __forceinline__ u64 f2mul(u64 a, u64 b) {
    u64 d; asm("mul.rn.f32x2 %0,%1,%2;" : "=l"(d) : "l"(a), "l"(b)); return d;
}
__device__ __forceinline__ u64 f2fma(u64 a, u64 b, u64 c) {
    u64 d; asm("fma.rn.f32x2 %0,%1,%2,%3;" : "=l"(d) : "l"(a), "l"(b), "l"(c)); return d;
}
__device__ __forceinline__ float frcp(float x) {        // single MUFU.RCP
    float r; asm("rcp.approx.f32 %0,%1;" : "=f"(r) : "f"(x)); return r;
}

// ---------------------------------------------------------------------------
// Kernel 1: Cauchy + Woodbury + bilinear (+ twiddle build on h==0 blocks).
// Identity: v/(z-w)+conj(v)/(z-conj(w)) = (alpha + i*beta*y)*g,
//   alpha=-2Re(v*conj(w)), beta=2Re(v) real; g=1/D, D=(|w|^2-y^2)-i(2wr)y.
// a1 = sum (alpha,beta)*gr ; a2 = sum (alpha,beta)*h, h=-gi.
//   re = a1.lo + y*a2.hi ; im = -a2.lo + y*a1.hi
// ILP=4: each thread handles l = l0 + {0,128,256,384} as 2 packed pairs.
// Grid (4, HDIM) x 128 threads; block covers 512 consecutive l.
// ---------------------------------------------------------------------------
__global__ void __launch_bounds__(128) cauchy_kernel(
                              const float* __restrict__ w_re, const float* __restrict__ w_im,
                              const float* __restrict__ p_re, const float* __restrict__ p_im,
                              const float* __restrict__ B_re, const float* __restrict__ B_im,
                              const float* __restrict__ C_re, const float* __restrict__ C_im,
                              const float* __restrict__ log_dt) {
    __shared__ u64 s_MM[NDIM], s_cc[NDIM];        // (|w|^2,|w|^2), (-2wr,-2wr)
    __shared__ u64 s_ab00[NDIM], s_ab01[NDIM];    // (alpha, beta) per row
    __shared__ u64 s_ab10[NDIM], s_ab11[NDIM];
    __shared__ float s_ny[NDIM];                  // v00r for Nyquist limit

    const int h   = blockIdx.y;
    const int tid = threadIdx.x;
    const float dt = expf(log_dt[h]);

    if (tid < NDIM) {
        const int idx = h * NDIM + tid;
        const float wr = w_re[idx] * dt, wi = w_im[idx] * dt;
        const float M = wr * wr + wi * wi, c = -2.0f * wr;
        s_MM[tid] = pk(M, M);
        s_cc[tid] = pk(c, c);
        const float br = B_re[idx], bi = B_im[idx];
        const float cr = C_re[idx], ci = C_im[idx];
        const float pr = p_re[idx], pi = p_im[idx];
        const float v00r = dt * (br * cr - bi * ci), v00i = dt * (br * ci + bi * cr);
        const float v01r = dt * (br * pr + bi * pi), v01i = dt * (bi * pr - br * pi);
        const float v10r = dt * (pr * cr - pi * ci), v10i = dt * (pr * ci + pi * cr);
        const float v11r = dt * (pr * pr + pi * pi);
        s_ab00[tid] = pk(-2.f * (v00r * wr + v00i * wi), 2.f * v00r);
        s_ab01[tid] = pk(-2.f * (v01r * wr + v01i * wi), 2.f * v01r);
        s_ab10[tid] = pk(-2.f * (v10r * wr + v10i * wi), 2.f * v10r);
        s_ab11[tid] = pk(-2.f * (v11r * wr),             2.f * v11r);
        s_ny[tid]   = v00r;
    }
    __syncthreads();

    const int l0 = blockIdx.x * 512 + tid;   // l = l0 + {0,128,256,384}

    float yv[4];
    #pragma unroll
    for (int j = 0; j < 4; j++)
        yv[j] = 2.0f * tanf((float)(l0 + 128 * j) * (float)(M_PI / (double)LLEN));
    u64 yP[2], ny2P[2];
    #pragma unroll
    for (int jp = 0; jp < 2; jp++) {
        yP[jp]   = pk(yv[2 * jp], yv[2 * jp + 1]);
        ny2P[jp] = pk(-yv[2 * jp] * yv[2 * jp], -yv[2 * jp + 1] * yv[2 * jp + 1]);
    }

    u64 a1_00[4] = {0,0,0,0}, a2_00[4] = {0,0,0,0};
    u64 a1_01[4] = {0,0,0,0}, a2_01[4] = {0,0,0,0};
    u64 a1_10[4] = {0,0,0,0}, a2_10[4] = {0,0,0,0};
    u64 a1_11[4] = {0,0,0,0}, a2_11[4] = {0,0,0,0};

    #pragma unroll 2
    for (int n = 0; n < NDIM; n++) {
        const u64 MM = s_MM[n], cc = s_cc[n];
        const u64 ab0 = s_ab00[n], ab1 = s_ab01[n], ab2 = s_ab10[n], ab3 = s_ab11[n];
        #pragma unroll
        for (int jp = 0; jp < 2; jp++) {
            const u64 DrP  = f2add(MM, ny2P[jp]);      // (Dr_a, Dr_b)
            const u64 DiP  = f2mul(cc, yP[jp]);        // (Di_a, Di_b)
            const u64 Dr2P = f2mul(DrP, DrP);
            const u64 denP = f2fma(DiP, DiP, Dr2P);
            float de0, de1; upk(de0, de1, denP);
            const u64 invP = pk(frcp(de0), frcp(de1));
            const u64 grP  = f2mul(DrP, invP);
            const u64 hP   = f2mul(DiP, invP);         // h = -gi
            float gr0, gr1; upk(gr0, gr1, grP);
            float h0,  h1;  upk(h0,  h1,  hP);
            const u64 ggA = pk(gr0, gr0), ggB = pk(gr1, gr1);
            const u64 hhA = pk(h0, h0),   hhB = pk(h1, h1);
            const int ja = 2 * jp, jb = 2 * jp + 1;
            a1_00[ja] = f2fma(ab0, ggA, a1_00[ja]);  a2_00[ja] = f2fma(ab0, hhA, a2_00[ja]);
            a1_01[ja] = f2fma(ab1, ggA, a1_01[ja]);  a2_01[ja] = f2fma(ab1, hhA, a2_01[ja]);
            a1_10[ja] = f2fma(ab2, ggA, a1_10[ja]);  a2_10[ja] = f2fma(ab2, hhA, a2_10[ja]);
            a1_11[ja] = f2fma(ab3, ggA, a1_11[ja]);  a2_11[ja] = f2fma(ab3, hhA, a2_11[ja]);
            a1_00[jb] = f2fma(ab0, ggB, a1_00[jb]);  a2_00[jb] = f2fma(ab0, hhB, a2_00[jb]);
            a1_01[jb] = f2fma(ab1, ggB, a1_01[jb]);  a2_01[jb] = f2fma(ab1, hhB, a2_01[jb]);
            a1_10[jb] = f2fma(ab2, ggB, a1_10[jb]);  a2_10[jb] = f2fma(ab2, hhB, a2_10[jb]);
            a1_11[jb] = f2fma(ab3, ggB, a1_11[jb]);  a2_11[jb] = f2fma(ab3, hhB, a2_11[jb]);
        }
    }

    #pragma unroll
    for (int j = 0; j < 4; j++) {
        const float y = yv[j];
        // re = a1.lo + y*a2.hi ; im = -a2.lo + y*a1.hi
        float g00, b00, i00, q00; upk(g00, b00, a1_00[j]); upk(i00, q00, a2_00[j]);
        float g01, b01, i01, q01; upk(g01, b01, a1_01[j]); upk(i01, q01, a2_01[j]);
        float g10, b10, i10, q10; upk(g10, b10, a1_10[j]); upk(i10, q10, a2_10[j]);
        float g11, b11, i11, q11; upk(g11, b11, a1_11[j]); upk(i11, q11, a2_11[j]);
        const float r00r = g00 + y * q00, r00i = -i00 + y * b00;
        const float r01r = g01 + y * q01, r01i = -i01 + y * b01;
        const float r10r = g10 + y * q10, r10i = -i10 + y * b10;
        const float r11r = g11 + y * q11, r11i = -i11 + y * b11;

        // Woodbury: k = r00 - r01*r10/(1+r11)
        const float dr = 1.f + r11r, di = r11i;
        const float dinv = frcp(fmaf(dr, dr, di * di));
        const float qr = r01r * r10r - r01i * r10i;
        const float qi = r01r * r10i + r01i * r10r;
        const float cr2 = (qr * dr + qi * di) * dinv;
        const float ci2 = (qi * dr - qr * di) * dinv;
        const float kr = r00r - cr2, ki = r00i - ci2;

        // scale by 2/(1+omega) = 1 + i*(y/2)
        const float hy = 0.5f * y;
        g_kf[h * LF + l0 + 128 * j] = make_float2(kr - hy * ki, ki + hy * kr);
    }

    if (blockIdx.x == 0 && tid == 0) {
        float acc = 0.f;
        #pragma unroll
        for (int n = 0; n < NDIM; n++) acc += s_ny[n];
        g_kf[h * LF + LLEN / 2] = make_float2(acc, 0.f);
    }

    // twiddle table: h==0 blocks (4 x 128 threads x 2 = 1024 entries)
    if (blockIdx.y == 0) {
        #pragma unroll
        for (int q = 0; q < 2; q++) {
            const int j = blockIdx.x * 128 + tid + q * 512;
            float s, c;
            sincosf((float)j * (float)(2.0 * M_PI / (double)LLEN), &s, &c);
            g_tw[j] = make_float2(c, s);
        }
    }
}

// ---------------------------------------------------------------------------
// Kernel 2: per-head 4096-pt inverse FFT, radix-4 DIT.
// Stage 0 fused into gmem load, stage 5 fused into gmem store,
// stages 1..4 in smem with XOR bank swizzle; w2/w3 computed from w1.
// ---------------------------------------------------------------------------
#define IX(i) ((i) ^ (((i) >> 4) & 15))

__global__ void __launch_bounds__(512) ifft_kernel(float* __restrict__ out) {
    __shared__ float2 X[LLEN];       // 32 KB (swizzled)
    __shared__ float2 TW[1024];      // 8 KB  (swizzled)

    const int h   = blockIdx.x;
    const int tid = threadIdx.x;

    #pragma unroll
    for (int j = tid; j < 1024; j += 512)
        TW[IX(j)] = g_tw[j];

    // fused digit-reversal load + stage 0 (twiddle-free radix-4)
    const float2* kf = &g_kf[h * LF];
    #pragma unroll 2
    for (int j = tid; j < 1024; j += 512) {
        const int br = __brev((unsigned)j) >> 22;                 // 10-bit reverse
        const int rj = ((br & 0x155) << 1) | ((br >> 1) & 0x155); // base-4 digit rev
        const float2 t0 = kf[rj];
        const float2 t1 = kf[1024 + rj];
        const float2 c2 = kf[2048 - rj];  const float2 t2 = make_float2(c2.x, -c2.y);
        const float2 c3 = kf[1024 - rj];  const float2 t3 = make_float2(c3.x, -c3.y);

        const float ax = t0.x + t2.x, ay = t0.y + t2.y;
        const float bx = t0.x - t2.x, by = t0.y - t2.y;
        const float cx = t1.x + t3.x, cy = t1.y + t3.y;
        const float dx = -(t1.y - t3.y), dy = t1.x - t3.x;

        const int base = 4 * j;
        X[IX(base)]     = make_float2(ax + cx, ay + cy);
        X[IX(base + 1)] = make_float2(bx + dx, by + dy);
        X[IX(base + 2)] = make_float2(ax - cx, ay - cy);
        X[IX(base + 3)] = make_float2(bx - dx, by - dy);
    }
    __syncthreads();

    // stages 1..4 in shared memory
    #pragma unroll
    for (int s = 1; s < 5; s++) {
        const int m    = 1 << (2 * s);
        const int step = 1024 >> (2 * s);
        #pragma unroll 2
        for (int j = tid; j < 1024; j += 512) {
            const int k    = j & (m - 1);
            const int base = ((j >> (2 * s)) << (2 * s + 2)) + k;
            const float2 t0 = X[IX(base)];
            const float2 x1 = X[IX(base + m)];
            const float2 x2 = X[IX(base + 2 * m)];
            const float2 x3 = X[IX(base + 3 * m)];

            const float2 w1 = TW[IX(k * step)];
            const float2 w2 = make_float2(w1.x * w1.x - w1.y * w1.y, 2.f * w1.x * w1.y);
            const float2 w3 = make_float2(w1.x * w2.x - w1.y * w2.y, w1.x * w2.y + w1.y * w2.x);

            const float2 t1 = make_float2(x1.x * w1.x - x1.y * w1.y, x1.x * w1.y + x1.y * w1.x);
            const float2 t2 = make_float2(x2.x * w2.x - x2.y * w2.y, x2.x * w2.y + x2.y * w2.x);
            const float2 t3 = make_float2(x3.x * w3.x - x3.y * w3.y, x3.x * w3.y + x3.y * w3.x);

            const float ax = t0.x + t2.x, ay = t0.y + t2.y;
            const float bx = t0.x - t2.x, by = t0.y - t2.y;
            const float cx = t1.x + t3.x, cy = t1.y + t3.y;
            const float dx = -(t1.y - t3.y), dy = t1.x - t3.x;

            X[IX(base)]         = make_float2(ax + cx, ay + cy);
            X[IX(base + m)]     = make_float2(bx + dx, by + dy);
            X[IX(base + 2 * m)] = make_float2(ax - cx, ay - cy);
            X[IX(base + 3 * m)] = make_float2(bx - dx, by - dy);
        }
        __syncthreads();
    }

    // stage 5 (m=1024) fused into the output store: only real parts needed
    const float scale = 1.0f / (float)LLEN;
    float* o = out + h * LLEN;
    #pragma unroll 2
    for (int j = tid; j < 1024; j += 512) {
        const int k = j;
        const float2 t0 = X[IX(k)];
        const float2 x1 = X[IX(k + 1024)];
        const float2 x2 = X[IX(k + 2048)];
        const float2 x3 = X[IX(k + 3072)];

        const float2 w1 = TW[IX(k)];
        const float2 w2 = make_float2(w1.x * w1.x - w1.y * w1.y, 2.f * w1.x * w1.y);
        const float2 w3 = make_float2(w1.x * w2.x - w1.y * w2.y, w1.x * w2.y + w1.y * w2.x);

        const float2 t1 = make_float2(x1.x * w1.x - x1.y * w1.y, x1.x * w1.y + x1.y * w1.x);
        const float2 t2 = make_float2(x2.x * w2.x - x2.y * w2.y, x2.x * w2.y + x2.y * w2.x);
        const float2 t3 = make_float2(x3.x * w3.x - x3.y * w3.y, x3.x * w3.y + x3.y * w3.x);

        const float ax = t0.x + t2.x;
        const float bx = t0.x - t2.x;
        const float cx = t1.x + t3.x;
        const float dx = -(t1.y - t3.y);

        o[k]        = (ax + cx) * scale;
        o[k + 1024] = (bx + dx) * scale;
        o[k + 2048] = (ax - cx) * scale;
        o[k + 3072] = (bx - dx) * scale;
    }
}

extern "C" void kernel_launch(void* const* d_in, const int* in_sizes, int n_in,
                              void* d_out, int out_size) {
    const float* w_re   = (const float*)d_in[0];
    const float* w_im   = (const float*)d_in[1];
    const float* p_re   = (const float*)d_in[2];
    const float* p_im   = (const float*)d_in[3];
    const float* B_re   = (const float*)d_in[4];
    const float* B_im   = (const float*)d_in[5];
    const float* C_re   = (const float*)d_in[6];
    const float* C_im   = (const float*)d_in[7];
    const float* log_dt = (const float*)d_in[8];
    float* out = (float*)d_out;

    dim3 g1(4, HDIM);
    cauchy_kernel<<<g1, 128>>>(w_re, w_im, p_re, p_im, B_re, B_im, C_re, C_im, log_dt);
    ifft_kernel<<<HDIM, 512>>>(out);
}

// round 11
// speedup vs baseline: 1.0810x; 1.0810x over previous
#include <cuda_runtime.h>
#include <cuda_bf16.h>
#include <math.h>

#define HDIM 512
#define NDIM 32
#define LLEN 4096
#define LF   2049   // LLEN/2 + 1

__device__ float2 g_kf[HDIM * LF];
__device__ float2 g_tw[1024];      // W^j = e^{+2*pi*i*j/4096}, j < 1024

// ---------------- packed f32x2 + fast-rcp helpers ---------------------------
typedef unsigned long long u64;
__device__ __forceinline__ u64 pk(float lo, float hi) {
    u64 r; asm("mov.b64 %0,{%1,%2};" : "=l"(r) : "f"(lo), "f"(hi)); return r;
}
__device__ __forceinline__ void upk(float& lo, float& hi, u64 v) {
    asm("mov.b64 {%0,%1},%2;" : "=f"(lo), "=f"(hi) : "l"(v));
}
__device__ __forceinline__ u64 f2add(u64 a, u64 b) {
    u64 d; asm("add.rn.f32x2 %0,%1,%2;" : "=l"(d) : "l"(a), "l"(b)); return d;
}
__device__ __forceinline__ u64 f2mul(u64 a, u64 b) {
    u64 d; asm("mul.rn.f32x2 %0,%1,%2;" : "=l"(d) : "l"(a), "l"(b)); return d;
}
__device__ __forceinline__ u64 f2fma(u64 a, u64 b, u64 c) {
    u64 d; asm("fma.rn.f32x2 %0,%1,%2,%3;" : "=l"(d) : "l"(a), "l"(b), "l"(c)); return d;
}
__device__ __forceinline__ float frcp(float x) {        // single MUFU.RCP
    float r; asm("rcp.approx.f32 %0,%1;" : "=f"(r) : "f"(x)); return r;
}

// ---------------------------------------------------------------------------
// Kernel 1: Cauchy + Woodbury + bilinear (+ twiddle build on h==0 blocks).
// (unchanged from R10 — at its FFMA2 roofline)
// ---------------------------------------------------------------------------
__global__ void __launch_bounds__(128) cauchy_kernel(
                              const float* __restrict__ w_re, const float* __restrict__ w_im,
                              const float* __restrict__ p_re, const float* __restrict__ p_im,
                              const float* __restrict__ B_re, const float* __restrict__ B_im,
                              const float* __restrict__ C_re, const float* __restrict__ C_im,
                              const float* __restrict__ log_dt) {
    __shared__ u64 s_MM[NDIM], s_cc[NDIM];
    __shared__ u64 s_ab00[NDIM], s_ab01[NDIM];
    __shared__ u64 s_ab10[NDIM], s_ab11[NDIM];
    __shared__ float s_ny[NDIM];

    const int h   = blockIdx.y;
    const int tid = threadIdx.x;
    const float dt = expf(log_dt[h]);

    if (tid < NDIM) {
        const int idx = h * NDIM + tid;
        const float wr = w_re[idx] * dt, wi = w_im[idx] * dt;
        const float M = wr * wr + wi * wi, c = -2.0f * wr;
        s_MM[tid] = pk(M, M);
        s_cc[tid] = pk(c, c);
        const float br = B_re[idx], bi = B_im[idx];
        const float cr = C_re[idx], ci = C_im[idx];
        const float pr = p_re[idx], pi = p_im[idx];
        const float v00r = dt * (br * cr - bi * ci), v00i = dt * (br * ci + bi * cr);
        const float v01r = dt * (br * pr + bi * pi), v01i = dt * (bi * pr - br * pi);
        const float v10r = dt * (pr * cr - pi * ci), v10i = dt * (pr * ci + pi * cr);
        const float v11r = dt * (pr * pr + pi * pi);
        s_ab00[tid] = pk(-2.f * (v00r * wr + v00i * wi), 2.f * v00r);
        s_ab01[tid] = pk(-2.f * (v01r * wr + v01i * wi), 2.f * v01r);
        s_ab10[tid] = pk(-2.f * (v10r * wr + v10i * wi), 2.f * v10r);
        s_ab11[tid] = pk(-2.f * (v11r * wr),             2.f * v11r);
        s_ny[tid]   = v00r;
    }
    __syncthreads();

    const int l0 = blockIdx.x * 512 + tid;   // l = l0 + {0,128,256,384}

    float yv[4];
    #pragma unroll
    for (int j = 0; j < 4; j++)
        yv[j] = 2.0f * tanf((float)(l0 + 128 * j) * (float)(M_PI / (double)LLEN));
    u64 yP[2], ny2P[2];
    #pragma unroll
    for (int jp = 0; jp < 2; jp++) {
        yP[jp]   = pk(yv[2 * jp], yv[2 * jp + 1]);
        ny2P[jp] = pk(-yv[2 * jp] * yv[2 * jp], -yv[2 * jp + 1] * yv[2 * jp + 1]);
    }

    u64 a1_00[4] = {0,0,0,0}, a2_00[4] = {0,0,0,0};
    u64 a1_01[4] = {0,0,0,0}, a2_01[4] = {0,0,0,0};
    u64 a1_10[4] = {0,0,0,0}, a2_10[4] = {0,0,0,0};
    u64 a1_11[4] = {0,0,0,0}, a2_11[4] = {0,0,0,0};

    #pragma unroll 2
    for (int n = 0; n < NDIM; n++) {
        const u64 MM = s_MM[n], cc = s_cc[n];
        const u64 ab0 = s_ab00[n], ab1 = s_ab01[n], ab2 = s_ab10[n], ab3 = s_ab11[n];
        #pragma unroll
        for (int jp = 0; jp < 2; jp++) {
            const u64 DrP  = f2add(MM, ny2P[jp]);
            const u64 DiP  = f2mul(cc, yP[jp]);
            const u64 Dr2P = f2mul(DrP, DrP);
            const u64 denP = f2fma(DiP, DiP, Dr2P);
            float de0, de1; upk(de0, de1, denP);
            const u64 invP = pk(frcp(de0), frcp(de1));
            const u64 grP  = f2mul(DrP, invP);
            const u64 hP   = f2mul(DiP, invP);
            float gr0, gr1; upk(gr0, gr1, grP);
            float h0,  h1;  upk(h0,  h1,  hP);
            const u64 ggA = pk(gr0, gr0), ggB = pk(gr1, gr1);
            const u64 hhA = pk(h0, h0),   hhB = pk(h1, h1);
            const int ja = 2 * jp, jb = 2 * jp + 1;
            a1_00[ja] = f2fma(ab0, ggA, a1_00[ja]);  a2_00[ja] = f2fma(ab0, hhA, a2_00[ja]);
            a1_01[ja] = f2fma(ab1, ggA, a1_01[ja]);  a2_01[ja] = f2fma(ab1, hhA, a2_01[ja]);
            a1_10[ja] = f2fma(ab2, ggA, a1_10[ja]);  a2_10[ja] = f2fma(ab2, hhA, a2_10[ja]);
            a1_11[ja] = f2fma(ab3, ggA, a1_11[ja]);  a2_11[ja] = f2fma(ab3, hhA, a2_11[ja]);
            a1_00[jb] = f2fma(ab0, ggB, a1_00[jb]);  a2_00[jb] = f2fma(ab0, hhB, a2_00[jb]);
            a1_01[jb] = f2fma(ab1, ggB, a1_01[jb]);  a2_01[jb] = f2fma(ab1, hhB, a2_01[jb]);
            a1_10[jb] = f2fma(ab2, ggB, a1_10[jb]);  a2_10[jb] = f2fma(ab2, hhB, a2_10[jb]);
            a1_11[jb] = f2fma(ab3, ggB, a1_11[jb]);  a2_11[jb] = f2fma(ab3, hhB, a2_11[jb]);
        }
    }

    #pragma unroll
    for (int j = 0; j < 4; j++) {
        const float y = yv[j];
        float g00, b00, i00, q00; upk(g00, b00, a1_00[j]); upk(i00, q00, a2_00[j]);
        float g01, b01, i01, q01; upk(g01, b01, a1_01[j]); upk(i01, q01, a2_01[j]);
        float g10, b10, i10, q10; upk(g10, b10, a1_10[j]); upk(i10, q10, a2_10[j]);
        float g11, b11, i11, q11; upk(g11, b11, a1_11[j]); upk(i11, q11, a2_11[j]);
        const float r00r = g00 + y * q00, r00i = -i00 + y * b00;
        const float r01r = g01 + y * q01, r01i = -i01 + y * b01;
        const float r10r = g10 + y * q10, r10i = -i10 + y * b10;
        const float r11r = g11 + y * q11, r11i = -i11 + y * b11;

        const float dr = 1.f + r11r, di = r11i;
        const float dinv = frcp(fmaf(dr, dr, di * di));
        const float qr = r01r * r10r - r01i * r10i;
        const float qi = r01r * r10i + r01i * r10r;
        const float cr2 = (qr * dr + qi * di) * dinv;
        const float ci2 = (qi * dr - qr * di) * dinv;
        const float kr = r00r - cr2, ki = r00i - ci2;

        const float hy = 0.5f * y;
        g_kf[h * LF + l0 + 128 * j] = make_float2(kr - hy * ki, ki + hy * kr);
    }

    if (blockIdx.x == 0 && tid == 0) {
        float acc = 0.f;
        #pragma unroll
        for (int n = 0; n < NDIM; n++) acc += s_ny[n];
        g_kf[h * LF + LLEN / 2] = make_float2(acc, 0.f);
    }

    if (blockIdx.y == 0) {
        #pragma unroll
        for (int q = 0; q < 2; q++) {
            const int j = blockIdx.x * 128 + tid + q * 512;
            float s, c;
            sincosf((float)j * (float)(2.0 * M_PI / (double)LLEN), &s, &c);
            g_tw[j] = make_float2(c, s);
        }
    }
}

// ---------------------------------------------------------------------------
// Kernel 2: per-head 4096-pt inverse FFT.
// Stage 0 fused into gmem load; stages 1+2 and 3+4 fused as register-resident
// radix-16 passes (16 float2 per thread); stage 5 fused into gmem store.
// X transits: 10 -> 6, barriers 6 -> 4.
// ---------------------------------------------------------------------------
#define IX(i) ((i) ^ (((i) >> 4) & 15))

__device__ __forceinline__ float2 cmul(float2 a, float2 b) {
    return make_float2(a.x * b.x - a.y * b.y, a.x * b.y + a.y * b.x);
}
// in-place inverse radix-4 butterfly; inputs x1,x2,x3 twiddled by w1,w2,w3
__device__ __forceinline__ void bfly4(float2& x0, float2& x1, float2& x2, float2& x3,
                                      float2 w1, float2 w2, float2 w3) {
    const float2 t0 = x0, t1 = cmul(x1, w1), t2 = cmul(x2, w2), t3 = cmul(x3, w3);
    const float ax = t0.x + t2.x, ay = t0.y + t2.y;
    const float bx = t0.x - t2.x, by = t0.y - t2.y;
    const float cx = t1.x + t3.x, cy = t1.y + t3.y;
    const float dx = -(t1.y - t3.y), dy = t1.x - t3.x;
    x0 = make_float2(ax + cx, ay + cy);
    x1 = make_float2(bx + dx, by + dy);
    x2 = make_float2(ax - cx, ay - cy);
    x3 = make_float2(bx - dx, by - dy);
}

__global__ void __launch_bounds__(256) ifft_kernel(float* __restrict__ out) {
    __shared__ float2 X[LLEN];       // 32 KB (swizzled)
    __shared__ float2 TW[1024];      // 8 KB  (swizzled)

    const int h   = blockIdx.x;
    const int tid = threadIdx.x;

    #pragma unroll
    for (int j = tid; j < 1024; j += 256)
        TW[IX(j)] = g_tw[j];

    // fused digit-reversal load + stage 0 (twiddle-free radix-4)
    const float2* kf = &g_kf[h * LF];
    #pragma unroll
    for (int j = tid; j < 1024; j += 256) {
        const int br = __brev((unsigned)j) >> 22;                 // 10-bit reverse
        const int rj = ((br & 0x155) << 1) | ((br >> 1) & 0x155); // base-4 digit rev
        const float2 t0 = kf[rj];
        const float2 t1 = kf[1024 + rj];
        const float2 c2 = kf[2048 - rj];  const float2 t2 = make_float2(c2.x, -c2.y);
        const float2 c3 = kf[1024 - rj];  const float2 t3 = make_float2(c3.x, -c3.y);

        const float ax = t0.x + t2.x, ay = t0.y + t2.y;
        const float bx = t0.x - t2.x, by = t0.y - t2.y;
        const float cx = t1.x + t3.x, cy = t1.y + t3.y;
        const float dx = -(t1.y - t3.y), dy = t1.x - t3.x;

        const int base = 4 * j;
        X[IX(base)]     = make_float2(ax + cx, ay + cy);
        X[IX(base + 1)] = make_float2(bx + dx, by + dy);
        X[IX(base + 2)] = make_float2(ax - cx, ay - cy);
        X[IX(base + 3)] = make_float2(bx - dx, by - dy);
    }
    __syncthreads();

    // ---- fused stages 1+2: thread owns elements {64B + r + 4t, t=0..15} ----
    {
        const int B = tid >> 2, r = tid & 3;
        const int eb = 64 * B + r;
        float2 x[16];
        #pragma unroll
        for (int t = 0; t < 16; t++) x[t] = X[IX(eb + 4 * t)];

        // stage 1 (m=4, step=256): k = r for all 4 butterflies
        {
            const float2 w1 = TW[IX(256 * r)];
            const float2 w2 = cmul(w1, w1);
            const float2 w3 = cmul(w1, w2);
            #pragma unroll
            for (int s = 0; s < 4; s++)
                bfly4(x[4 * s], x[4 * s + 1], x[4 * s + 2], x[4 * s + 3], w1, w2, w3);
        }
        // stage 2 (m=16, step=64): k = r + 4*s
        #pragma unroll
        for (int s = 0; s < 4; s++) {
            const float2 w1 = TW[IX(64 * (r + 4 * s))];
            const float2 w2 = cmul(w1, w1);
            const float2 w3 = cmul(w1, w2);
            bfly4(x[s], x[s + 4], x[s + 8], x[s + 12], w1, w2, w3);
        }
        #pragma unroll
        for (int t = 0; t < 16; t++) X[IX(eb + 4 * t)] = x[t];
    }
    __syncthreads();

    // ---- fused stages 3+4: thread owns elements {1024*B2 + r2 + 64t} ----
    {
        const int B2 = tid >> 6, r2 = tid & 63;
        const int eb = 1024 * B2 + r2;
        float2 x[16];
        #pragma unroll
        for (int t = 0; t < 16; t++) x[t] = X[IX(eb + 64 * t)];

        // stage 3 (m=64, step=16): k = r2 for all 4 butterflies
        {
            const float2 w1 = TW[IX(16 * r2)];
            const float2 w2 = cmul(w1, w1);
            const float2 w3 = cmul(w1, w2);
            #pragma unroll
            for (int s = 0; s < 4; s++)
                bfly4(x[4 * s], x[4 * s + 1], x[4 * s + 2], x[4 * s + 3], w1, w2, w3);
        }
        // stage 4 (m=256, step=4): k = r2 + 64*s
        #pragma unroll
        for (int s = 0; s < 4; s++) {
            const float2 w1 = TW[IX(4 * (r2 + 64 * s))];
            const float2 w2 = cmul(w1, w1);
            const float2 w3 = cmul(w1, w2);
            bfly4(x[s], x[s + 4], x[s + 8], x[s + 12], w1, w2, w3);
        }
        #pragma unroll
        for (int t = 0; t < 16; t++) X[IX(eb + 64 * t)] = x[t];
    }
    __syncthreads();

    // stage 5 (m=1024, step=1) fused into the output store: real parts only
    const float scale = 1.0f / (float)LLEN;
    float* o = out + h * LLEN;
    #pragma unroll
    for (int j = tid; j < 1024; j += 256) {
        const int k = j;
        const float2 t0 = X[IX(k)];
        const float2 x1 = X[IX(k + 1024)];
        const float2 x2 = X[IX(k + 2048)];
        const float2 x3 = X[IX(k + 3072)];

        const float2 w1 = TW[IX(k)];
        const float2 w2 = cmul(w1, w1);
        const float2 w3 = cmul(w1, w2);

        const float2 t1 = cmul(x1, w1);
        const float2 t2 = cmul(x2, w2);
        const float2 t3 = cmul(x3, w3);

        const float ax = t0.x + t2.x;
        const float bx = t0.x - t2.x;
        const float cx = t1.x + t3.x;
        const float dx = -(t1.y - t3.y);

        o[k]        = (ax + cx) * scale;
        o[k + 1024] = (bx + dx) * scale;
        o[k + 2048] = (ax - cx) * scale;
        o[k + 3072] = (bx - dx) * scale;
    }
}

extern "C" void kernel_launch(void* const* d_in, const int* in_sizes, int n_in,
                              void* d_out, int out_size) {
    const float* w_re   = (const float*)d_in[0];
    const float* w_im   = (const float*)d_in[1];
    const float* p_re   = (const float*)d_in[2];
    const float* p_im   = (const float*)d_in[3];
    const float* B_re   = (const float*)d_in[4];
    const float* B_im   = (const float*)d_in[5];
    const float* C_re   = (const float*)d_in[6];
    const float* C_im   = (const float*)d_in[7];
    const float* log_dt = (const float*)d_in[8];
    float* out = (float*)d_out;

    dim3 g1(4, HDIM);
    cauchy_kernel<<<g1, 128>>>(w_re, w_im, p_re, p_im, B_re, B_im, C_re, C_im, log_dt);
    ifft_kernel<<<HDIM, 256>>>(out);
}

// round 12
// speedup vs baseline: 1.1219x; 1.0378x over previous
#include <cuda_runtime.h>
#include <cuda_bf16.h>
#include <math.h>

#define HDIM 512
#define NDIM 32
#define LLEN 4096
#define LF   2049   // LLEN/2 + 1

__device__ float2 g_kf[HDIM * LF];
__device__ float2 g_tw[1024];      // W^j = e^{+2*pi*i*j/4096}, j < 1024

// ---------------- packed f32x2 + fast-rcp helpers ---------------------------
typedef unsigned long long u64;
__device__ __forceinline__ u64 pk(float lo, float hi) {
    u64 r; asm("mov.b64 %0,{%1,%2};" : "=l"(r) : "f"(lo), "f"(hi)); return r;
}
__device__ __forceinline__ void upk(float& lo, float& hi, u64 v) {
    asm("mov.b64 {%0,%1},%2;" : "=f"(lo), "=f"(hi) : "l"(v));
}
__device__ __forceinline__ u64 f2add(u64 a, u64 b) {
    u64 d; asm("add.rn.f32x2 %0,%1,%2;" : "=l"(d) : "l"(a), "l"(b)); return d;
}
__device__ __forceinline__ u64 f2mul(u64 a, u64 b) {
    u64 d; asm("mul.rn.f32x2 %0,%1,%2;" : "=l"(d) : "l"(a), "l"(b)); return d;
}
__device__ __forceinline__ u64 f2fma(u64 a, u64 b, u64 c) {
    u64 d; asm("fma.rn.f32x2 %0,%1,%2,%3;" : "=l"(d) : "l"(a), "l"(b), "l"(c)); return d;
}
__device__ __forceinline__ float frcp(float x) {        // single MUFU.RCP
    float r; asm("rcp.approx.f32 %0,%1;" : "=f"(r) : "f"(x)); return r;
}

// ---------------------------------------------------------------------------
// Kernel 1: Cauchy + Woodbury + bilinear (+ twiddle build on h==0 blocks).
// (unchanged — at its FFMA2 roofline)
// ---------------------------------------------------------------------------
__global__ void __launch_bounds__(128) cauchy_kernel(
                              const float* __restrict__ w_re, const float* __restrict__ w_im,
                              const float* __restrict__ p_re, const float* __restrict__ p_im,
                              const float* __restrict__ B_re, const float* __restrict__ B_im,
                              const float* __restrict__ C_re, const float* __restrict__ C_im,
                              const float* __restrict__ log_dt) {
    __shared__ u64 s_MM[NDIM], s_cc[NDIM];
    __shared__ u64 s_ab00[NDIM], s_ab01[NDIM];
    __shared__ u64 s_ab10[NDIM], s_ab11[NDIM];
    __shared__ float s_ny[NDIM];

    const int h   = blockIdx.y;
    const int tid = threadIdx.x;
    const float dt = expf(log_dt[h]);

    if (tid < NDIM) {
        const int idx = h * NDIM + tid;
        const float wr = w_re[idx] * dt, wi = w_im[idx] * dt;
        const float M = wr * wr + wi * wi, c = -2.0f * wr;
        s_MM[tid] = pk(M, M);
        s_cc[tid] = pk(c, c);
        const float br = B_re[idx], bi = B_im[idx];
        const float cr = C_re[idx], ci = C_im[idx];
        const float pr = p_re[idx], pi = p_im[idx];
        const float v00r = dt * (br * cr - bi * ci), v00i = dt * (br * ci + bi * cr);
        const float v01r = dt * (br * pr + bi * pi), v01i = dt * (bi * pr - br * pi);
        const float v10r = dt * (pr * cr - pi * ci), v10i = dt * (pr * ci + pi * cr);
        const float v11r = dt * (pr * pr + pi * pi);
        s_ab00[tid] = pk(-2.f * (v00r * wr + v00i * wi), 2.f * v00r);
        s_ab01[tid] = pk(-2.f * (v01r * wr + v01i * wi), 2.f * v01r);
        s_ab10[tid] = pk(-2.f * (v10r * wr + v10i * wi), 2.f * v10r);
        s_ab11[tid] = pk(-2.f * (v11r * wr),             2.f * v11r);
        s_ny[tid]   = v00r;
    }
    __syncthreads();

    const int l0 = blockIdx.x * 512 + tid;   // l = l0 + {0,128,256,384}

    float yv[4];
    #pragma unroll
    for (int j = 0; j < 4; j++)
        yv[j] = 2.0f * tanf((float)(l0 + 128 * j) * (float)(M_PI / (double)LLEN));
    u64 yP[2], ny2P[2];
    #pragma unroll
    for (int jp = 0; jp < 2; jp++) {
        yP[jp]   = pk(yv[2 * jp], yv[2 * jp + 1]);
        ny2P[jp] = pk(-yv[2 * jp] * yv[2 * jp], -yv[2 * jp + 1] * yv[2 * jp + 1]);
    }

    u64 a1_00[4] = {0,0,0,0}, a2_00[4] = {0,0,0,0};
    u64 a1_01[4] = {0,0,0,0}, a2_01[4] = {0,0,0,0};
    u64 a1_10[4] = {0,0,0,0}, a2_10[4] = {0,0,0,0};
    u64 a1_11[4] = {0,0,0,0}, a2_11[4] = {0,0,0,0};

    #pragma unroll 2
    for (int n = 0; n < NDIM; n++) {
        const u64 MM = s_MM[n], cc = s_cc[n];
        const u64 ab0 = s_ab00[n], ab1 = s_ab01[n], ab2 = s_ab10[n], ab3 = s_ab11[n];
        #pragma unroll
        for (int jp = 0; jp < 2; jp++) {
            const u64 DrP  = f2add(MM, ny2P[jp]);
            const u64 DiP  = f2mul(cc, yP[jp]);
            const u64 Dr2P = f2mul(DrP, DrP);
            const u64 denP = f2fma(DiP, DiP, Dr2P);
            float de0, de1; upk(de0, de1, denP);
            const u64 invP = pk(frcp(de0), frcp(de1));
            const u64 grP  = f2mul(DrP, invP);
            const u64 hP   = f2mul(DiP, invP);
            float gr0, gr1; upk(gr0, gr1, grP);
            float h0,  h1;  upk(h0,  h1,  hP);
            const u64 ggA = pk(gr0, gr0), ggB = pk(gr1, gr1);
            const u64 hhA = pk(h0, h0),   hhB = pk(h1, h1);
            const int ja = 2 * jp, jb = 2 * jp + 1;
            a1_00[ja] = f2fma(ab0, ggA, a1_00[ja]);  a2_00[ja] = f2fma(ab0, hhA, a2_00[ja]);
            a1_01[ja] = f2fma(ab1, ggA, a1_01[ja]);  a2_01[ja] = f2fma(ab1, hhA, a2_01[ja]);
            a1_10[ja] = f2fma(ab2, ggA, a1_10[ja]);  a2_10[ja] = f2fma(ab2, hhA, a2_10[ja]);
            a1_11[ja] = f2fma(ab3, ggA, a1_11[ja]);  a2_11[ja] = f2fma(ab3, hhA, a2_11[ja]);
            a1_00[jb] = f2fma(ab0, ggB, a1_00[jb]);  a2_00[jb] = f2fma(ab0, hhB, a2_00[jb]);
            a1_01[jb] = f2fma(ab1, ggB, a1_01[jb]);  a2_01[jb] = f2fma(ab1, hhB, a2_01[jb]);
            a1_10[jb] = f2fma(ab2, ggB, a1_10[jb]);  a2_10[jb] = f2fma(ab2, hhB, a2_10[jb]);
            a1_11[jb] = f2fma(ab3, ggB, a1_11[jb]);  a2_11[jb] = f2fma(ab3, hhB, a2_11[jb]);
        }
    }

    #pragma unroll
    for (int j = 0; j < 4; j++) {
        const float y = yv[j];
        float g00, b00, i00, q00; upk(g00, b00, a1_00[j]); upk(i00, q00, a2_00[j]);
        float g01, b01, i01, q01; upk(g01, b01, a1_01[j]); upk(i01, q01, a2_01[j]);
        float g10, b10, i10, q10; upk(g10, b10, a1_10[j]); upk(i10, q10, a2_10[j]);
        float g11, b11, i11, q11; upk(g11, b11, a1_11[j]); upk(i11, q11, a2_11[j]);
        const float r00r = g00 + y * q00, r00i = -i00 + y * b00;
        const float r01r = g01 + y * q01, r01i = -i01 + y * b01;
        const float r10r = g10 + y * q10, r10i = -i10 + y * b10;
        const float r11r = g11 + y * q11, r11i = -i11 + y * b11;

        const float dr = 1.f + r11r, di = r11i;
        const float dinv = frcp(fmaf(dr, dr, di * di));
        const float qr = r01r * r10r - r01i * r10i;
        const float qi = r01r * r10i + r01i * r10r;
        const float cr2 = (qr * dr + qi * di) * dinv;
        const float ci2 = (qi * dr - qr * di) * dinv;
        const float kr = r00r - cr2, ki = r00i - ci2;

        const float hy = 0.5f * y;
        g_kf[h * LF + l0 + 128 * j] = make_float2(kr - hy * ki, ki + hy * kr);
    }

    if (blockIdx.x == 0 && tid == 0) {
        float acc = 0.f;
        #pragma unroll
        for (int n = 0; n < NDIM; n++) acc += s_ny[n];
        g_kf[h * LF + LLEN / 2] = make_float2(acc, 0.f);
    }

    if (blockIdx.y == 0) {
        #pragma unroll
        for (int q = 0; q < 2; q++) {
            const int j = blockIdx.x * 128 + tid + q * 512;
            float s, c;
            sincosf((float)j * (float)(2.0 * M_PI / (double)LLEN), &s, &c);
            g_tw[j] = make_float2(c, s);
        }
    }
}

// ---------------------------------------------------------------------------
// Kernel 2: per-head 4096-pt inverse FFT as THREE radix-16 passes.
//  pass 1: stages 0+1 fused with gmem hermitian gather (stage-1 twiddles are
//          compile-time constants W^{256k});  writes X once.
//  pass 2: stages 2+3 on {256B + r + 16t}.
//  pass 3: stages 4+5 on {r3 + 256t} fused with the real-part gmem store.
// X transits: 4, barriers: 2.
// ---------------------------------------------------------------------------
#define IX(i) ((i) ^ (((i) >> 4) & 15))

__device__ __forceinline__ float2 cmul(float2 a, float2 b) {
    return make_float2(a.x * b.x - a.y * b.y, a.x * b.y + a.y * b.x);
}
__device__ __forceinline__ void bfly4(float2& x0, float2& x1, float2& x2, float2& x3,
                                      float2 w1, float2 w2, float2 w3) {
    const float2 t0 = x0, t1 = cmul(x1, w1), t2 = cmul(x2, w2), t3 = cmul(x3, w3);
    const float ax = t0.x + t2.x, ay = t0.y + t2.y;
    const float bx = t0.x - t2.x, by = t0.y - t2.y;
    const float cx = t1.x + t3.x, cy = t1.y + t3.y;
    const float dx = -(t1.y - t3.y), dy = t1.x - t3.x;
    x0 = make_float2(ax + cx, ay + cy);
    x1 = make_float2(bx + dx, by + dy);
    x2 = make_float2(ax - cx, ay - cy);
    x3 = make_float2(bx - dx, by - dy);
}
// radix-4 with unity twiddles
__device__ __forceinline__ void bfly4u(float2 t0, float2 t1, float2 t2, float2 t3,
                                       float2& y0, float2& y1, float2& y2, float2& y3) {
    const float ax = t0.x + t2.x, ay = t0.y + t2.y;
    const float bx = t0.x - t2.x, by = t0.y - t2.y;
    const float cx = t1.x + t3.x, cy = t1.y + t3.y;
    const float dx = -(t1.y - t3.y), dy = t1.x - t3.x;
    y0 = make_float2(ax + cx, ay + cy);
    y1 = make_float2(bx + dx, by + dy);
    y2 = make_float2(ax - cx, ay - cy);
    y3 = make_float2(bx - dx, by - dy);
}

__global__ void __launch_bounds__(256) ifft_kernel(float* __restrict__ out) {
    __shared__ float2 X[LLEN];       // 32 KB (swizzled)
    __shared__ float2 TW[1024];      // 8 KB  (swizzled)

    const int h   = blockIdx.x;
    const int tid = threadIdx.x;

    #pragma unroll
    for (int j = tid; j < 1024; j += 256)
        TW[IX(j)] = g_tw[j];

    // ---- pass 1: stages 0+1, thread J owns outputs {16J + u} --------------
    {
        // stage-1 twiddles: W^{256k} = e^{i*pi*k/8}, k=0..3 (constants)
        const float C8 = 0.92387953251128674f, S8 = 0.38268343236508978f;
        const float CQ = 0.70710678118654752f;
        const float2 W1[4] = {{1.f,0.f},{C8,S8},{CQ,CQ},{S8,C8}};
        const float2 W2[4] = {{1.f,0.f},{CQ,CQ},{0.f,1.f},{-CQ,CQ}};
        const float2 W3[4] = {{1.f,0.f},{S8,C8},{-CQ,CQ},{-C8,-S8}};

        const int J = tid;
        const float2* kf = &g_kf[h * LF];
        float2 x[16];
        #pragma unroll
        for (int p = 0; p < 4; p++) {
            const int j = 4 * J + p;
            const int br = __brev((unsigned)j) >> 22;                 // 10-bit rev
            const int rj = ((br & 0x155) << 1) | ((br >> 1) & 0x155); // base-4 rev
            const float2 t0 = kf[rj];
            const float2 t1 = kf[1024 + rj];
            const float2 c2 = kf[2048 - rj];  const float2 t2 = make_float2(c2.x, -c2.y);
            const float2 c3 = kf[1024 - rj];  const float2 t3 = make_float2(c3.x, -c3.y);
            bfly4u(t0, t1, t2, t3, x[4 * p], x[4 * p + 1], x[4 * p + 2], x[4 * p + 3]);
        }
        // stage 1: butterflies k=0..3 over (x[k], x[k+4], x[k+8], x[k+12])
        #pragma unroll
        for (int k = 0; k < 4; k++)
            bfly4(x[k], x[k + 4], x[k + 8], x[k + 12], W1[k], W2[k], W3[k]);
        #pragma unroll
        for (int u = 0; u < 16; u++) X[IX(16 * J + u)] = x[u];
    }
    __syncthreads();

    // ---- pass 2: stages 2+3 on {256B + r + 16t} ---------------------------
    {
        const int B = tid >> 4, r = tid & 15;
        const int eb = 256 * B + r;
        float2 x[16];
        #pragma unroll
        for (int t = 0; t < 16; t++) x[t] = X[IX(eb + 16 * t)];

        // stage 2 (m=16, step=64): k = r shared by all 4 butterflies
        {
            const float2 w1 = TW[IX(64 * r)];
            const float2 w2 = cmul(w1, w1);
            const float2 w3 = cmul(w1, w2);
            #pragma unroll
            for (int p = 0; p < 4; p++)
                bfly4(x[4 * p], x[4 * p + 1], x[4 * p + 2], x[4 * p + 3], w1, w2, w3);
        }
        // stage 3 (m=64, step=16): k = r + 16*t0
        #pragma unroll
        for (int t0 = 0; t0 < 4; t0++) {
            const float2 w1 = TW[IX(16 * (r + 16 * t0))];
            const float2 w2 = cmul(w1, w1);
            const float2 w3 = cmul(w1, w2);
            bfly4(x[t0], x[t0 + 4], x[t0 + 8], x[t0 + 12], w1, w2, w3);
        }
        #pragma unroll
        for (int t = 0; t < 16; t++) X[IX(eb + 16 * t)] = x[t];
    }
    __syncthreads();

    // ---- pass 3: stages 4+5 on {r3 + 256t}, fused real-part store ---------
    {
        const int r3 = tid;
        float2 x[16];
        #pragma unroll
        for (int t = 0; t < 16; t++) x[t] = X[IX(r3 + 256 * t)];

        // stage 4 (m=256, step=4): k = r3 shared by all 4 butterflies
        {
            const float2 w1 = TW[IX(4 * r3)];
            const float2 w2 = cmul(w1, w1);
            const float2 w3 = cmul(w1, w2);
            #pragma unroll
            for (int p = 0; p < 4; p++)
                bfly4(x[4 * p], x[4 * p + 1], x[4 * p + 2], x[4 * p + 3], w1, w2, w3);
        }
        // stage 5 (m=1024, step=1): k = r3 + 256*t0; real parts only
        const float scale = 1.0f / (float)LLEN;
        float* o = out + h * LLEN;
        #pragma unroll
        for (int t0 = 0; t0 < 4; t0++) {
            const int k = r3 + 256 * t0;
            const float2 w1 = TW[IX(k)];
            const float2 w2 = cmul(w1, w1);
            const float2 w3 = cmul(w1, w2);
            const float2 t0v = x[t0];
            const float2 t1 = cmul(x[t0 + 4],  w1);
            const float2 t2 = cmul(x[t0 + 8],  w2);
            const float2 t3 = cmul(x[t0 + 12], w3);
            const float ax = t0v.x + t2.x;
            const float bx = t0v.x - t2.x;
            const float cx = t1.x + t3.x;
            const float dx = -(t1.y - t3.y);
            o[k]        = (ax + cx) * scale;
            o[k + 1024] = (bx + dx) * scale;
            o[k + 2048] = (ax - cx) * scale;
            o[k + 3072] = (bx - dx) * scale;
        }
    }
}

extern "C" void kernel_launch(void* const* d_in, const int* in_sizes, int n_in,
                              void* d_out, int out_size) {
    const float* w_re   = (const float*)d_in[0];
    const float* w_im   = (const float*)d_in[1];
    const float* p_re   = (const float*)d_in[2];
    const float* p_im   = (const float*)d_in[3];
    const float* B_re   = (const float*)d_in[4];
    const float* B_im   = (const float*)d_in[5];
    const float* C_re   = (const float*)d_in[6];
    const float* C_im   = (const float*)d_in[7];
    const float* log_dt = (const float*)d_in[8];
    float* out = (float*)d_out;

    dim3 g1(4, HDIM);
    cauchy_kernel<<<g1, 128>>>(w_re, w_im, p_re, p_im, B_re, B_im, C_re, C_im, log_dt);
    ifft_kernel<<<HDIM, 256>>>(out);
}